// round 2
// baseline (speedup 1.0000x reference)
#include <cuda_runtime.h>
#include <cstdint>
#include <cstddef>

// ---------------- constants ----------------
#define NSEG        2368
#define NSEG_L1     2048          // layer1: m(2) x o(128) x chunk(8), 128 cols each
#define SEG_W2      2048          // +128 segs, 512 cols
#define SEG_W3      2176          // +64 segs, 128 cols
#define SEG_WOUT    2240          // +128 segs, 64 cols
#define LIST_MAX    344064        // fully dense upper bound (can never overflow)
#define LIST_SM     16384         // smem staging capacity (entries)
#define ACTS        1.3333333730697632f

// ---------------- device scratch (static, allowed) ----------------
__device__ int   d_scale_bits[5];
__device__ int   d_cnt[NSEG];
__device__ int   d_off[NSEG + 1];
__device__ short d_list[LIST_MAX];

// ---------------- prep: init ----------------
__global__ void prep_init() {
    if (threadIdx.x < 5) d_scale_bits[threadIdx.x] = 0;
}

// ---------------- prep: per-tensor max|w| (exact, via atomicMax on bits) ----------------
__global__ void prep_scale(const float* __restrict__ W1a, const float* __restrict__ W1b,
                           const float* __restrict__ W2,  const float* __restrict__ W3,
                           const float* __restrict__ Wout)
{
    __shared__ float red[8];
    int m = blockIdx.x >> 5;
    int part = blockIdx.x & 31;
    const float* W; int n;
    switch (m) {
        case 0: W = W1a;  n = 131072; break;
        case 1: W = W1b;  n = 131072; break;
        case 2: W = W2;   n = 65536;  break;
        case 3: W = W3;   n = 8192;   break;
        default: W = Wout; n = 8192;  break;
    }
    int chunk = n >> 5;
    int lo = part * chunk;
    float mx = 0.0f;
    for (int i = lo + threadIdx.x; i < lo + chunk; i += 256)
        mx = fmaxf(mx, fabsf(W[i]));
    #pragma unroll
    for (int o = 16; o; o >>= 1) mx = fmaxf(mx, __shfl_xor_sync(0xffffffffu, mx, o));
    if ((threadIdx.x & 31) == 0) red[threadIdx.x >> 5] = mx;
    __syncthreads();
    if (threadIdx.x < 32) {
        float v = (threadIdx.x < 8) ? red[threadIdx.x] : 0.0f;
        #pragma unroll
        for (int o = 4; o; o >>= 1) v = fmaxf(v, __shfl_xor_sync(0xffffffffu, v, o));
        if (threadIdx.x == 0) atomicMax(&d_scale_bits[m], __float_as_int(v));
    }
}

// ---------------- segment decode (count/fill) ----------------
struct SegInfo { const float* rowp; int len; float s; bool l1; };

__device__ __forceinline__ SegInfo seg_decode(int seg,
    const float* W1a, const float* W1b, const float* W2,
    const float* W3, const float* Wout)
{
    SegInfo r;
    if (seg < NSEG_L1) {
        int m = seg >> 10, rem = seg & 1023;
        int o = rem >> 3, c = rem & 7;
        r.rowp = (m ? W1b : W1a) + o * 1024 + c * 128;
        r.len = 128; r.s = __int_as_float(d_scale_bits[m]); r.l1 = true;
    } else if (seg < SEG_W3) {
        r.rowp = W2 + (seg - SEG_W2) * 512;
        r.len = 512; r.s = __int_as_float(d_scale_bits[2]); r.l1 = false;
    } else if (seg < SEG_WOUT) {
        r.rowp = W3 + (seg - SEG_W3) * 128;
        r.len = 128; r.s = __int_as_float(d_scale_bits[3]); r.l1 = false;
    } else {
        r.rowp = Wout + (seg - SEG_WOUT) * 64;
        r.len = 64; r.s = __int_as_float(d_scale_bits[4]); r.l1 = false;
    }
    return r;
}

// ---------------- prep: count nnz per segment (one warp / segment) ----------------
__global__ void prep_count(const float* __restrict__ W1a, const float* __restrict__ W1b,
                           const float* __restrict__ W2,  const float* __restrict__ W3,
                           const float* __restrict__ Wout)
{
    int lane = threadIdx.x & 31;
    int seg = blockIdx.x * 8 + (threadIdx.x >> 5);
    if (seg >= NSEG) return;
    SegInfo si = seg_decode(seg, W1a, W1b, W2, W3, Wout);
    int cnt = 0;
    for (int j0 = 0; j0 < si.len; j0 += 32) {
        float w = si.rowp[j0 + lane];
        float q = rintf(__fdiv_rn(w, si.s));
        unsigned bal = __ballot_sync(0xffffffffu, q != 0.0f);
        cnt += __popc(bal);
    }
    if (lane == 0) d_cnt[seg] = cnt;
}

// ---------------- prep: exclusive scan (single block, Hillis-Steele over 4096) ----------------
__global__ void prep_scan() {
    __shared__ int sa[4096], sb[4096];
    int tid = threadIdx.x;
    for (int i = tid; i < 4096; i += 1024) sa[i] = (i < NSEG) ? d_cnt[i] : 0;
    __syncthreads();
    int* src = sa; int* dst = sb;
    for (int off = 1; off < 4096; off <<= 1) {
        for (int i = tid; i < 4096; i += 1024)
            dst[i] = src[i] + (i >= off ? src[i - off] : 0);
        __syncthreads();
        int* t = src; src = dst; dst = t;
    }
    for (int i = tid; i <= NSEG; i += 1024)
        d_off[i] = (i == 0) ? 0 : src[i - 1];
}

// ---------------- prep: fill compacted sign/index lists ----------------
__global__ void prep_fill(const float* __restrict__ W1a, const float* __restrict__ W1b,
                          const float* __restrict__ W2,  const float* __restrict__ W3,
                          const float* __restrict__ Wout)
{
    int lane = threadIdx.x & 31;
    int seg = blockIdx.x * 8 + (threadIdx.x >> 5);
    if (seg >= NSEG) return;
    SegInfo si = seg_decode(seg, W1a, W1b, W2, W3, Wout);
    int base = d_off[seg];
    for (int j0 = 0; j0 < si.len; j0 += 32) {
        float w = si.rowp[j0 + lane];
        float q = rintf(__fdiv_rn(w, si.s));
        bool nz = (q != 0.0f);
        unsigned bal = __ballot_sync(0xffffffffu, nz);
        if (nz) {
            int pos = base + __popc(bal & ((1u << lane) - 1u));
            int idx = j0 + lane;
            int e = si.l1 ? (idx * 33 + 1) : (idx + 1);   // layer1 pre-scaled by smem stride
            d_list[pos] = (short)(q < 0.0f ? -e : e);
        }
        base += __popc(bal);
    }
}

// ---------------- main kernel ----------------
// smem layout (bytes):
//  XS0  @ 0      : 128*33*4  = 16896   (x tile buf0, transposed, stride 33)
//  XS1  @ 16896  : 16896               (x tile buf1)
//  H1   @ 33792  : 32*516    = 16512   (h1 codes, row stride 516)
//  H2   @ 50304  : 32*132    = 4224
//  H3   @ 54528  : 32*68     = 2176
//  OFF  @ 56704  : 2369*4    = 9476
//  LIST @ 66180  : 16384*2   = 32768
//  total = 98948 ; OUTS (32*132*4 = 16896) aliases XS0
#define SMEM_BYTES 98948

__global__ void __launch_bounds__(512, 2) mlp_main(
    const float* __restrict__ x,
    const float* __restrict__ b1a, const float* __restrict__ b1b,
    const float* __restrict__ b2,  const float* __restrict__ b3,
    float* __restrict__ out)
{
    extern __shared__ unsigned char smem[];
    float* xs0 = (float*)(smem);
    float* xs1 = (float*)(smem + 16896);
    unsigned char* h1s = smem + 33792;
    unsigned char* h2s = smem + 50304;
    unsigned char* h3s = smem + 54528;
    int*   s_off  = (int*)(smem + 56704);
    short* s_list = (short*)(smem + 66180);
    float* outs   = (float*)(smem);          // alias XS0 (free after last tile)

    const int tid  = threadIdx.x;
    const int r    = tid & 31;        // batch row within tile
    const int g    = tid >> 5;        // output group (warp id), 0..15
    const int row0 = blockIdx.x << 5;

    const float sc1a = __int_as_float(d_scale_bits[0]);
    const float sc1b = __int_as_float(d_scale_bits[1]);
    const float s2   = __int_as_float(d_scale_bits[2]);
    const float s3   = __int_as_float(d_scale_bits[3]);
    const float s4   = __int_as_float(d_scale_bits[4]);

    for (int i = tid; i <= NSEG; i += 512) s_off[i] = d_off[i];
    const int total = d_off[NSEG];
    const bool use_sm = (total <= LIST_SM);
    if (use_sm)
        for (int i = tid; i < total; i += 512) s_list[i] = d_list[i];
    const short* lst = use_sm ? (const short*)s_list : (const short*)d_list;

    // preload tile 0
    float pref[8];
    {
        const float* xb = x + (size_t)row0 * 4096;
        #pragma unroll
        for (int k = 0; k < 8; k++) {
            int i = tid + (k << 9); int rr = i >> 7; int cc = i & 127;
            pref[k] = __ldcs(xb + (size_t)rr * 4096 + cc);
        }
        #pragma unroll
        for (int k = 0; k < 8; k++) {
            int i = tid + (k << 9); int rr = i >> 7; int cc = i & 127;
            xs0[cc * 33 + rr] = pref[k];
        }
    }
    __syncthreads();

    float acc[8];
    #pragma unroll
    for (int j = 0; j < 8; j++) acc[j] = 0.0f;

    // ---- layer 1: 4 branches x 8 chunks of 128 cols ----
    for (int t = 0; t < 32; ++t) {
        const int branch = t >> 3, chunk = t & 7, m = branch & 1;

        if (t + 1 < 32) {   // prefetch next tile into registers
            int nb = (t + 1) >> 3, nc = (t + 1) & 7;
            const float* xb = x + (size_t)row0 * 4096 + nb * 1024 + nc * 128;
            #pragma unroll
            for (int k = 0; k < 8; k++) {
                int i = tid + (k << 9); int rr = i >> 7; int cc = i & 127;
                pref[k] = __ldcs(xb + (size_t)rr * 4096 + cc);
            }
        }

        const float* cur = (t & 1) ? xs1 : xs0;
        const float  sc  = m ? sc1b : sc1a;
        #pragma unroll
        for (int j = 0; j < 8; j++) {
            int o  = (g << 3) + j;
            int seg = (m << 10) + (o << 3) + chunk;
            int p0 = s_off[seg], p1 = s_off[seg + 1];
            float a = acc[j];
            for (int p = p0; p < p1; ++p) {
                int v  = lst[p];
                int av = (v < 0) ? -v : v;             // = idx*33 + 1
                a = fmaf((v < 0) ? -sc : sc, cur[av - 1 + r], a);
            }
            acc[j] = a;
        }

        if (chunk == 7) {   // end of branch -> quantize 8 outputs
            const float* bb = m ? b1b : b1a;
            #pragma unroll
            for (int j = 0; j < 8; j++) {
                int o = (g << 3) + j;
                float y = acc[j] + bb[o];
                float qv = rintf(__fdiv_rn(y, ACTS));
                qv = fminf(fmaxf(qv, 0.0f), 3.0f);
                h1s[r * 516 + (branch << 7) + o] = (unsigned char)(int)qv;
                acc[j] = 0.0f;
            }
        }
        __syncthreads();
        if (t + 1 < 32) {
            float* nxt = (t & 1) ? xs0 : xs1;
            #pragma unroll
            for (int k = 0; k < 8; k++) {
                int i = tid + (k << 9); int rr = i >> 7; int cc = i & 127;
                nxt[cc * 33 + rr] = pref[k];
            }
            __syncthreads();
        }
    }
    __syncthreads();

    // ---- layer 2: 512 -> 128 (integer code accumulation, exact) ----
    #pragma unroll
    for (int j = 0; j < 8; j++) {
        int o = (g << 3) + j;
        int seg = SEG_W2 + o;
        int p0 = s_off[seg], p1 = s_off[seg + 1];
        int is = 0;
        for (int p = p0; p < p1; ++p) {
            int v = lst[p];
            int av = ((v < 0) ? -v : v) - 1;
            int c = h1s[r * 516 + av];
            is += (v < 0) ? -c : c;
        }
        float y = fmaf((float)is * ACTS, s2, b2[o]);
        float qv = rintf(__fdiv_rn(y, ACTS));
        qv = fminf(fmaxf(qv, 0.0f), 3.0f);
        h2s[r * 132 + o] = (unsigned char)(int)qv;
    }
    __syncthreads();

    // ---- layer 3: 128 -> 64 ----
    #pragma unroll
    for (int j = 0; j < 4; j++) {
        int o = (g << 2) + j;
        int seg = SEG_W3 + o;
        int p0 = s_off[seg], p1 = s_off[seg + 1];
        int is = 0;
        for (int p = p0; p < p1; ++p) {
            int v = lst[p];
            int av = ((v < 0) ? -v : v) - 1;
            int c = h2s[r * 132 + av];
            is += (v < 0) ? -c : c;
        }
        float y = fmaf((float)is * ACTS, s3, b3[o]);
        float qv = rintf(__fdiv_rn(y, ACTS));
        qv = fminf(fmaxf(qv, 0.0f), 3.0f);
        h3s[r * 68 + o] = (unsigned char)(int)qv;
    }
    __syncthreads();

    // ---- output layer: 64 -> 128, no bias ----
    #pragma unroll
    for (int j = 0; j < 8; j++) {
        int o = (g << 3) + j;
        int seg = SEG_WOUT + o;
        int p0 = s_off[seg], p1 = s_off[seg + 1];
        int is = 0;
        for (int p = p0; p < p1; ++p) {
            int v = lst[p];
            int av = ((v < 0) ? -v : v) - 1;
            int c = h3s[r * 68 + av];
            is += (v < 0) ? -c : c;
        }
        outs[r * 132 + o] = ((float)is * ACTS) * s4;
    }
    __syncthreads();

    // coalesced float4 store
    #pragma unroll
    for (int k = 0; k < 2; k++) {
        int q = tid + (k << 9);
        int rr = q >> 5, c4 = q & 31;
        float4 v = *(const float4*)&outs[rr * 132 + (c4 << 2)];
        *(float4*)&out[(size_t)(row0 + rr) * 128 + (c4 << 2)] = v;
    }
}

// ---------------- launch ----------------
extern "C" void kernel_launch(void* const* d_in, const int* in_sizes, int n_in,
                              void* d_out, int out_size)
{
    const float* x    = (const float*)d_in[0];
    const float* W1a  = (const float*)d_in[1];
    const float* b1a  = (const float*)d_in[2];
    const float* W1b  = (const float*)d_in[3];
    const float* b1b  = (const float*)d_in[4];
    const float* W2   = (const float*)d_in[5];
    const float* b2   = (const float*)d_in[6];
    const float* W3   = (const float*)d_in[7];
    const float* b3   = (const float*)d_in[8];
    const float* Wout = (const float*)d_in[9];
    float* out = (float*)d_out;

    prep_init<<<1, 32>>>();
    prep_scale<<<160, 256>>>(W1a, W1b, W2, W3, Wout);
    prep_count<<<NSEG / 8, 256>>>(W1a, W1b, W2, W3, Wout);
    prep_scan<<<1, 1024>>>();
    prep_fill<<<NSEG / 8, 256>>>(W1a, W1b, W2, W3, Wout);

    cudaFuncSetAttribute(mlp_main, cudaFuncAttributeMaxDynamicSharedMemorySize, SMEM_BYTES);
    mlp_main<<<1024, 512, SMEM_BYTES>>>(x, b1a, b1b, b2, b3, out);
}